// round 13
// baseline (speedup 1.0000x reference)
#include <cuda_runtime.h>
#include <cuda_bf16.h>
#include <math.h>
#include <stdint.h>

#define NMAX   50000
#define EMAX   800000
#define ETOT   (NMAX + EMAX)
#define HDIM   256
#define DMAX   768
#define NEG_SLOPE 0.2f
#define EPS    1e-16f

// ---------------- scratch ----------------
__device__ float g_bufA[(size_t)NMAX * HDIM];
__device__ float g_bufB[(size_t)NMAX * HDIM];
__device__ __nv_bfloat16 g_xh[(size_t)NMAX * DMAX];
__device__ __nv_bfloat16 g_xl[(size_t)NMAX * DMAX];
__device__ __nv_bfloat16 g_hh[(size_t)NMAX * HDIM];
__device__ __nv_bfloat16 g_hl[(size_t)NMAX * HDIM];
__device__ __nv_bfloat16 g_wth[HDIM * DMAX];
__device__ __nv_bfloat16 g_wtl[HDIM * DMAX];
__device__ __nv_bfloat16 g_wth2[HDIM * HDIM];
__device__ __nv_bfloat16 g_wtl2[HDIM * HDIM];
__device__ float g_asrc[NMAX];
__device__ float g_adst[NMAX];
__device__ float g_gate[NMAX];
__device__ int   g_counts[NMAX];
__device__ int   g_fill[NMAX];
__device__ int   g_rowptr[NMAX + 1];
__device__ int   g_csrc[ETOT];
__device__ int   g_bsum[256];
__device__ int   g_boff[256];
__device__ float g_stats[2];
__device__ float g_partial[256 * 256];

// ---------------- helpers ----------------
__device__ __forceinline__ uint32_t s2u(const void* p) {
    uint32_t a;
    asm("{ .reg .u64 t; cvta.to.shared.u64 t, %1; cvt.u32.u64 %0, t; }" : "=r"(a) : "l"(p));
    return a;
}
__device__ __forceinline__ uint32_t b2u(__nv_bfloat16 a, __nv_bfloat16 b) {
    uint16_t ua = *(uint16_t*)&a, ub = *(uint16_t*)&b;
    return (uint32_t)ua | ((uint32_t)ub << 16);
}
__device__ __forceinline__ void ldsm4(uint32_t& r0, uint32_t& r1, uint32_t& r2,
                                      uint32_t& r3, uint32_t addr) {
    asm volatile("ldmatrix.sync.aligned.m8n8.x4.shared.b16 {%0,%1,%2,%3}, [%4];"
                 : "=r"(r0), "=r"(r1), "=r"(r2), "=r"(r3) : "r"(addr));
}
#define MMA_BF16(c, a, b) \
    asm volatile("mma.sync.aligned.m16n8k16.row.col.f32.bf16.bf16.f32 " \
        "{%0,%1,%2,%3}, {%4,%5,%6,%7}, {%8,%9}, {%0,%1,%2,%3};" \
        : "+f"((c)[0]), "+f"((c)[1]), "+f"((c)[2]), "+f"((c)[3]) \
        : "r"((a)[0]), "r"((a)[1]), "r"((a)[2]), "r"((a)[3]), \
          "r"((b)[0]), "r"((b)[1]))
#define CP16(dst, src, sz) \
    asm volatile("cp.async.cg.shared.global [%0], [%1], 16, %2;" \
                 :: "r"(dst), "l"(src), "r"(sz) : "memory")
#define CP_COMMIT() asm volatile("cp.async.commit_group;" ::: "memory")
#define CP_WAIT2()  asm volatile("cp.async.wait_group 2;" ::: "memory")
#define CP_WAIT1()  asm volatile("cp.async.wait_group 1;" ::: "memory")
#define CP_WAIT0()  asm volatile("cp.async.wait_group 0;" ::: "memory")

// ---------------- fp32 -> bf16 hi/lo split (planar) ----------------
__global__ void k_split(const float* __restrict__ in, __nv_bfloat16* __restrict__ hi,
                        __nv_bfloat16* __restrict__ lo, int total4) {
    int i = blockIdx.x * blockDim.x + threadIdx.x;
    if (i >= total4) return;
    float4 v = ((const float4*)in)[i];
    float f[4] = {v.x, v.y, v.z, v.w};
    __nv_bfloat16 h[4], l[4];
#pragma unroll
    for (int j = 0; j < 4; j++) {
        h[j] = __float2bfloat16_rn(f[j]);
        l[j] = __float2bfloat16_rn(f[j] - __bfloat162float(h[j]));
    }
    ((uint2*)hi)[i] = make_uint2(b2u(h[0], h[1]), b2u(h[2], h[3]));
    ((uint2*)lo)[i] = make_uint2(b2u(l[0], l[1]), b2u(l[2], l[3]));
}

// ---------------- CSR build ----------------
__global__ void k_init_counts(int N) {
    int i = blockIdx.x * blockDim.x + threadIdx.x;
    if (i < N) { g_counts[i] = 1; g_fill[i] = 0; }
}
__global__ void k_hist(const int* __restrict__ ei, int E) {
    int e = blockIdx.x * blockDim.x + threadIdx.x;
    if (e < E) atomicAdd(&g_counts[ei[E + e]], 1);
}
__global__ void k_scan1(int N) {
    __shared__ int red[256];
    int t = threadIdx.x;
    int i = blockIdx.x * 256 + t;
    red[t] = (i < N) ? g_counts[i] : 0;
    __syncthreads();
    for (int off = 128; off > 0; off >>= 1) {
        if (t < off) red[t] += red[t + off];
        __syncthreads();
    }
    if (t == 0) g_bsum[blockIdx.x] = red[0];
}
__global__ void k_scan2(int nb) {
    __shared__ int s[256];
    int t = threadIdx.x;
    s[t] = (t < nb) ? g_bsum[t] : 0;
    __syncthreads();
    for (int off = 1; off < 256; off <<= 1) {
        int v = s[t];
        int add = (t >= off) ? s[t - off] : 0;
        __syncthreads();
        s[t] = v + add;
        __syncthreads();
    }
    if (t < nb) g_boff[t] = (t == 0) ? 0 : s[t - 1];
}
__global__ void k_scan3(int N) {
    __shared__ int s[256];
    int t = threadIdx.x;
    int i = blockIdx.x * 256 + t;
    int c = (i < N) ? g_counts[i] : 0;
    s[t] = c;
    __syncthreads();
    for (int off = 1; off < 256; off <<= 1) {
        int v = s[t];
        int add = (t >= off) ? s[t - off] : 0;
        __syncthreads();
        s[t] = v + add;
        __syncthreads();
    }
    if (i < N) {
        int excl = g_boff[blockIdx.x] + s[t] - c;
        g_rowptr[i] = excl;
        if (i == N - 1) g_rowptr[N] = excl + c;
    }
}
__global__ void k_scatter(const int* __restrict__ ei, int N, int E) {
    int i = blockIdx.x * blockDim.x + threadIdx.x;
    if (i >= N + E) return;
    int s, d;
    if (i < N) { s = i; d = i; }
    else { s = ei[i - N]; d = ei[E + i - N]; }
    int pos = g_rowptr[d] + atomicAdd(&g_fill[d], 1);
    g_csrc[pos] = s;
}

// ---------------- weight transpose + split ----------------
__global__ void k_transpose_split(const float* __restrict__ W,
                                  __nv_bfloat16* __restrict__ WTh,
                                  __nv_bfloat16* __restrict__ WTl, int K, int N) {
    __shared__ float t[32][33];
    int bx = blockIdx.x * 32, by = blockIdx.y * 32;
    int tx = threadIdx.x, ty = threadIdx.y;
#pragma unroll
    for (int j = 0; j < 4; j++) {
        int k = by + ty + j * 8;
        if (k < K && bx + tx < N) t[ty + j * 8][tx] = W[(size_t)k * N + bx + tx];
    }
    __syncthreads();
#pragma unroll
    for (int j = 0; j < 4; j++) {
        int n = bx + ty + j * 8;
        int k = by + tx;
        if (n < N && k < K) {
            float v = t[tx][ty + j * 8];
            __nv_bfloat16 h = __float2bfloat16_rn(v);
            WTh[(size_t)n * K + k] = h;
            WTl[(size_t)n * K + k] = __float2bfloat16_rn(v - __bfloat162float(h));
        }
    }
}

// ---------------- 3xBF16 tensor-core GEMM, 3-stage cp.async pipeline ----------------
#define ROWB 80
#define OFF_AH 0
#define OFF_AL 10240
#define OFF_BH 20480
#define OFF_BL 30720
#define BUFSZ  40960
#define SMEM_GEMM (3 * BUFSZ)

extern __shared__ __align__(16) uint8_t smx[];

__global__ __launch_bounds__(256) void k_gemm_bf16(
        const __nv_bfloat16* __restrict__ Ah, const __nv_bfloat16* __restrict__ Al,
        const __nv_bfloat16* __restrict__ Bh, const __nv_bfloat16* __restrict__ Bl,
        float* __restrict__ C, int M, int K) {
    uint32_t sb = s2u(smx);
    int tid = threadIdx.x;
    int lane = tid & 31, wid = tid >> 5;
    int warp_m = wid >> 2, warp_n = wid & 3;
    int m0 = blockIdx.x * 128, n0 = blockIdx.y * 128;
    int rowsValid = M - m0;
    int nch = K >> 5;

    float c[4][4][4];
#pragma unroll
    for (int i = 0; i < 4; i++)
#pragma unroll
        for (int j = 0; j < 4; j++)
#pragma unroll
            for (int r = 0; r < 4; r++) c[i][j][r] = 0.f;

    int um0 = tid >> 2, ukb = tid & 3;
    int r16 = lane & 15, cblk = lane >> 4;
    uint32_t aBase = (uint32_t)(warp_m * 64 + r16) * ROWB + cblk * 16;
    uint32_t bn = (lane & 7) + ((lane >> 4) << 3);
    uint32_t bkb = (lane >> 3) & 1;
    uint32_t bBase = (uint32_t)(warp_n * 32 + bn) * ROWB + bkb * 16;

    auto stage = [&](int cch, uint32_t bufbase) {
#pragma unroll
        for (int i = 0; i < 2; i++) {
            int m = um0 + i * 64;
            uint32_t doff = bufbase + m * ROWB + ukb * 16;
            uint32_t szA = (m < rowsValid) ? 16u : 0u;
            const __nv_bfloat16* pA = Ah + (size_t)(m0 + m) * K + cch * 32 + ukb * 8;
            const __nv_bfloat16* pAl = Al + (size_t)(m0 + m) * K + cch * 32 + ukb * 8;
            CP16(sb + OFF_AH + doff, pA, szA);
            CP16(sb + OFF_AL + doff, pAl, szA);
            const __nv_bfloat16* pB = Bh + (size_t)(n0 + m) * K + cch * 32 + ukb * 8;
            const __nv_bfloat16* pBl = Bl + (size_t)(n0 + m) * K + cch * 32 + ukb * 8;
            CP16(sb + OFF_BH + doff, pB, 16u);
            CP16(sb + OFF_BL + doff, pBl, 16u);
        }
    };

    // prologue: prefetch chunks 0 and 1
    stage(0, 0);
    CP_COMMIT();
    if (nch > 1) {
        stage(1, BUFSZ);
        CP_COMMIT();
    }

    for (int cch = 0; cch < nch; cch++) {
        uint32_t cur = (uint32_t)(cch % 3) * BUFSZ;
        if (cch + 2 < nch) {
            stage(cch + 2, (uint32_t)((cch + 2) % 3) * BUFSZ);
            CP_COMMIT();
            CP_WAIT2();
        } else if (cch + 1 < nch) {
            CP_WAIT1();
        } else {
            CP_WAIT0();
        }
        __syncthreads();

#pragma unroll
        for (int kt = 0; kt < 2; kt++) {
            uint32_t ah[4][4], al[4][4], bh[4][2], bl[4][2];
#pragma unroll
            for (int mi = 0; mi < 4; mi++) {
                uint32_t off = cur + aBase + (uint32_t)(mi * 16) * ROWB + kt * 32;
                ldsm4(ah[mi][0], ah[mi][1], ah[mi][2], ah[mi][3], sb + OFF_AH + off);
                ldsm4(al[mi][0], al[mi][1], al[mi][2], al[mi][3], sb + OFF_AL + off);
            }
#pragma unroll
            for (int np = 0; np < 2; np++) {
                uint32_t off = cur + bBase + (uint32_t)(np * 16) * ROWB + kt * 32;
                ldsm4(bh[np * 2][0], bh[np * 2][1], bh[np * 2 + 1][0], bh[np * 2 + 1][1],
                      sb + OFF_BH + off);
                ldsm4(bl[np * 2][0], bl[np * 2][1], bl[np * 2 + 1][0], bl[np * 2 + 1][1],
                      sb + OFF_BL + off);
            }
#pragma unroll
            for (int mi = 0; mi < 4; mi++)
#pragma unroll
                for (int ni = 0; ni < 4; ni++) {
                    MMA_BF16(c[mi][ni], ah[mi], bh[ni]);
                    MMA_BF16(c[mi][ni], ah[mi], bl[ni]);
                    MMA_BF16(c[mi][ni], al[mi], bh[ni]);
                }
        }
        __syncthreads();
    }

    int g = lane >> 2, t4 = lane & 3;
#pragma unroll
    for (int mi = 0; mi < 4; mi++) {
#pragma unroll
        for (int ni = 0; ni < 4; ni++) {
            int m = m0 + warp_m * 64 + mi * 16 + g;
            int n = n0 + warp_n * 32 + ni * 8 + t4 * 2;
            if (m < M)
                *(float2*)(C + (size_t)m * HDIM + n) = make_float2(c[mi][ni][0], c[mi][ni][1]);
            if (m + 8 < M)
                *(float2*)(C + (size_t)(m + 8) * HDIM + n) = make_float2(c[mi][ni][2], c[mi][ni][3]);
        }
    }
}

// ---------------- warp-per-node attention scalars ----------------
__global__ __launch_bounds__(256) void k_attw(const float* __restrict__ h,
                                              const float* __restrict__ vs,
                                              const float* __restrict__ vd, int N) {
    int wid = threadIdx.x >> 5, lane = threadIdx.x & 31;
    int n = blockIdx.x * 8 + wid;
    if (n >= N) return;
    const float4* p = (const float4*)(h + (size_t)n * HDIM + lane * 8);
    float4 v0 = p[0], v1 = p[1];
    const float4* s = (const float4*)(vs + lane * 8);
    const float4* d = (const float4*)(vd + lane * 8);
    float4 s0 = s[0], s1 = s[1], d0 = d[0], d1 = d[1];
    float a_s = v0.x * s0.x + v0.y * s0.y + v0.z * s0.z + v0.w * s0.w
              + v1.x * s1.x + v1.y * s1.y + v1.z * s1.z + v1.w * s1.w;
    float a_d = v0.x * d0.x + v0.y * d0.y + v0.z * d0.z + v0.w * d0.w
              + v1.x * d1.x + v1.y * d1.y + v1.z * d1.z + v1.w * d1.w;
#pragma unroll
    for (int off = 16; off > 0; off >>= 1) {
        a_s += __shfl_xor_sync(0xffffffff, a_s, off);
        a_d += __shfl_xor_sync(0xffffffff, a_d, off);
    }
    if (lane == 0) { g_asrc[n] = a_s; g_adst[n] = a_d; }
}

// ---------------- warp-per-node edge softmax + aggregation ----------------
__global__ __launch_bounds__(256) void k_aggw(
        const float* __restrict__ hin, const float* __restrict__ bias,
        float* __restrict__ hout, __nv_bfloat16* __restrict__ oh,
        __nv_bfloat16* __restrict__ ol, const float* __restrict__ gw,
        const float* __restrict__ gb, int N, int do_split, int do_gate) {
    int wid = threadIdx.x >> 5, lane = threadIdx.x & 31;
    int n = blockIdx.x * 8 + wid;
    if (n >= N) return;
    int begin = g_rowptr[n], end = g_rowptr[n + 1];
    float ad = g_adst[n];

    float m = -1e30f;
    for (int e = begin + lane; e < end; e += 32) {
        float v = g_asrc[g_csrc[e]] + ad;
        v = v > 0.f ? v : NEG_SLOPE * v;
        m = fmaxf(m, v);
    }
#pragma unroll
    for (int off = 16; off > 0; off >>= 1)
        m = fmaxf(m, __shfl_xor_sync(0xffffffff, m, off));

    float4 acc0 = make_float4(0.f, 0.f, 0.f, 0.f);
    float4 acc1 = make_float4(0.f, 0.f, 0.f, 0.f);
    float lsum = 0.f;
    for (int eb = begin; eb < end; eb += 32) {
        int e = eb + lane;
        int cnt = min(32, end - eb);
        float w = 0.f;
        int sreg = 0;
        if (e < end) {
            sreg = g_csrc[e];
            float v = g_asrc[sreg] + ad;
            v = v > 0.f ? v : NEG_SLOPE * v;
            w = expf(v - m);
            lsum += w;
        }
        for (int j = 0; j < cnt; j++) {
            float wj = __shfl_sync(0xffffffff, w, j);
            int sj = __shfl_sync(0xffffffff, sreg, j);
            const float4* p = (const float4*)(hin + (size_t)sj * HDIM + lane * 8);
            float4 v0 = p[0], v1 = p[1];
            acc0.x += wj * v0.x; acc0.y += wj * v0.y;
            acc0.z += wj * v0.z; acc0.w += wj * v0.w;
            acc1.x += wj * v1.x; acc1.y += wj * v1.y;
            acc1.z += wj * v1.z; acc1.w += wj * v1.w;
        }
    }
#pragma unroll
    for (int off = 16; off > 0; off >>= 1)
        lsum += __shfl_xor_sync(0xffffffff, lsum, off);
    float inv = 1.f / (lsum + EPS);

    const float4* b4 = (const float4*)(bias + lane * 8);
    float4 bb0 = b4[0], bb1 = b4[1];
    float4 o0, o1;
    o0.x = fmaxf(acc0.x * inv + bb0.x, 0.f);
    o0.y = fmaxf(acc0.y * inv + bb0.y, 0.f);
    o0.z = fmaxf(acc0.z * inv + bb0.z, 0.f);
    o0.w = fmaxf(acc0.w * inv + bb0.w, 0.f);
    o1.x = fmaxf(acc1.x * inv + bb1.x, 0.f);
    o1.y = fmaxf(acc1.y * inv + bb1.y, 0.f);
    o1.z = fmaxf(acc1.z * inv + bb1.z, 0.f);
    o1.w = fmaxf(acc1.w * inv + bb1.w, 0.f);
    float4* po = (float4*)(hout + (size_t)n * HDIM + lane * 8);
    po[0] = o0; po[1] = o1;

    if (do_split) {
        float f[8] = {o0.x, o0.y, o0.z, o0.w, o1.x, o1.y, o1.z, o1.w};
        uint32_t hw[4], lw[4];
#pragma unroll
        for (int i = 0; i < 4; i++) {
            __nv_bfloat16 ha = __float2bfloat16_rn(f[2 * i]);
            __nv_bfloat16 hb = __float2bfloat16_rn(f[2 * i + 1]);
            hw[i] = b2u(ha, hb);
            lw[i] = b2u(__float2bfloat16_rn(f[2 * i] - __bfloat162float(ha)),
                        __float2bfloat16_rn(f[2 * i + 1] - __bfloat162float(hb)));
        }
        *(uint4*)(oh + (size_t)n * HDIM + lane * 8) = make_uint4(hw[0], hw[1], hw[2], hw[3]);
        *(uint4*)(ol + (size_t)n * HDIM + lane * 8) = make_uint4(lw[0], lw[1], lw[2], lw[3]);
    }
    if (do_gate) {
        const float4* g4 = (const float4*)(gw + lane * 8);
        float4 gg0 = g4[0], gg1 = g4[1];
        float gd = o0.x * gg0.x + o0.y * gg0.y + o0.z * gg0.z + o0.w * gg0.w
                 + o1.x * gg1.x + o1.y * gg1.y + o1.z * gg1.z + o1.w * gg1.w;
#pragma unroll
        for (int off = 16; off > 0; off >>= 1)
            gd += __shfl_xor_sync(0xffffffff, gd, off);
        if (lane == 0) g_gate[n] = gd + gb[0];
    }
}

// ---------------- global attention pooling ----------------
__global__ void k_softmax_stats(int N) {
    __shared__ float red[1024];
    int t = threadIdx.x;
    float m = -1e30f;
    for (int i = t; i < N; i += 1024) m = fmaxf(m, g_gate[i]);
    red[t] = m; __syncthreads();
    for (int off = 512; off > 0; off >>= 1) {
        if (t < off) red[t] = fmaxf(red[t], red[t + off]);
        __syncthreads();
    }
    m = red[0];
    __syncthreads();
    float s = 0.f;
    for (int i = t; i < N; i += 1024) s += expf(g_gate[i] - m);
    red[t] = s; __syncthreads();
    for (int off = 512; off > 0; off >>= 1) {
        if (t < off) red[t] += red[t + off];
        __syncthreads();
    }
    if (t == 0) { g_stats[0] = m; g_stats[1] = red[0]; }
}
__global__ void k_ga_partial(const float* __restrict__ h, int N) {
    int b = blockIdx.x, t = threadIdx.x;
    float m = g_stats[0], S = g_stats[1];
    float acc = 0.f;
    for (int n = b; n < N; n += 256)
        acc += (expf(g_gate[n] - m) / S) * h[(size_t)n * HDIM + t];
    g_partial[b * 256 + t] = acc;
}
__global__ void k_ga_final(float* __restrict__ out) {
    int t = threadIdx.x;
    float acc = 0.f;
    for (int b = 0; b < 256; b++) acc += g_partial[b * 256 + t];
    out[t] = acc;
}

// ---------------- launch ----------------
extern "C" void kernel_launch(void* const* d_in, const int* in_sizes, int n_in,
                              void* d_out, int out_size) {
    const float* x   = (const float*)d_in[0];
    const int*   ei  = (const int*)d_in[1];
    const float* W1  = (const float*)d_in[2];
    const float* b1  = (const float*)d_in[3];
    const float* as1 = (const float*)d_in[4];
    const float* ad1 = (const float*)d_in[5];
    const float* W2  = (const float*)d_in[6];
    const float* b2  = (const float*)d_in[7];
    const float* as2 = (const float*)d_in[8];
    const float* ad2 = (const float*)d_in[9];
    const float* gw  = (const float*)d_in[10];
    const float* gb  = (const float*)d_in[11];
    float*       out = (float*)d_out;

    const int D = 768;
    const int N = in_sizes[0] / D;
    const int E = in_sizes[1] / 2;

    float *bufA, *bufB;
    __nv_bfloat16 *xh, *xl, *hh, *hl, *wth, *wtl, *wth2, *wtl2;
    cudaGetSymbolAddress((void**)&bufA, g_bufA);
    cudaGetSymbolAddress((void**)&bufB, g_bufB);
    cudaGetSymbolAddress((void**)&xh, g_xh);
    cudaGetSymbolAddress((void**)&xl, g_xl);
    cudaGetSymbolAddress((void**)&hh, g_hh);
    cudaGetSymbolAddress((void**)&hl, g_hl);
    cudaGetSymbolAddress((void**)&wth, g_wth);
    cudaGetSymbolAddress((void**)&wtl, g_wtl);
    cudaGetSymbolAddress((void**)&wth2, g_wth2);
    cudaGetSymbolAddress((void**)&wtl2, g_wtl2);

    cudaFuncSetAttribute(k_gemm_bf16, cudaFuncAttributeMaxDynamicSharedMemorySize,
                         SMEM_GEMM);

    static cudaStream_t s1 = nullptr, s2 = nullptr;
    static cudaEvent_t e0 = nullptr, e1 = nullptr, e2 = nullptr;
    if (s1 == nullptr) {
        cudaStreamCreateWithFlags(&s1, cudaStreamNonBlocking);
        cudaStreamCreateWithFlags(&s2, cudaStreamNonBlocking);
        cudaEventCreateWithFlags(&e0, cudaEventDisableTiming);
        cudaEventCreateWithFlags(&e1, cudaEventDisableTiming);
        cudaEventCreateWithFlags(&e2, cudaEventDisableTiming);
    }

    int total4 = N * D / 4;
    int nb = (N + 255) / 256;
    dim3 gg((N + 127) / 128, 2);
    int gw8 = (N + 7) / 8;

    // fork
    cudaEventRecord(e0, 0);
    cudaStreamWaitEvent(s1, e0, 0);
    cudaStreamWaitEvent(s2, e0, 0);

    // s1: CSR build chain
    k_init_counts<<<nb, 256, 0, s1>>>(N);
    k_hist<<<(E + 255) / 256, 256, 0, s1>>>(ei, E);
    k_scan1<<<nb, 256, 0, s1>>>(N);
    k_scan2<<<1, 256, 0, s1>>>(nb);
    k_scan3<<<nb, 256, 0, s1>>>(N);
    k_scatter<<<(N + E + 255) / 256, 256, 0, s1>>>(ei, N, E);
    cudaEventRecord(e1, s1);

    // s2: weight transposes
    k_transpose_split<<<dim3(HDIM / 32, D / 32), dim3(32, 8), 0, s2>>>(W1, wth, wtl, D, HDIM);
    k_transpose_split<<<dim3(HDIM / 32, HDIM / 32), dim3(32, 8), 0, s2>>>(W2, wth2, wtl2, HDIM, HDIM);
    cudaEventRecord(e2, s2);

    // main: split x, layer 1
    k_split<<<(total4 + 255) / 256, 256>>>(x, xh, xl, total4);
    cudaStreamWaitEvent(0, e2, 0);
    k_gemm_bf16<<<gg, 256, SMEM_GEMM>>>(xh, xl, wth, wtl, bufA, N, D);
    k_attw<<<gw8, 256>>>(bufA, as1, ad1, N);
    cudaStreamWaitEvent(0, e1, 0);
    k_aggw<<<gw8, 256>>>(bufA, b1, bufB, hh, hl, gw, gb, N, 1, 0);

    // layer 2
    k_gemm_bf16<<<gg, 256, SMEM_GEMM>>>(hh, hl, wth2, wtl2, bufA, N, HDIM);
    k_attw<<<gw8, 256>>>(bufA, as2, ad2, N);
    k_aggw<<<gw8, 256>>>(bufA, b2, bufB, hh, hl, gw, gb, N, 0, 1);

    // pooling
    k_softmax_stats<<<1, 1024>>>(N);
    k_ga_partial<<<256, 256>>>(bufB, N);
    k_ga_final<<<1, 256>>>(out);
}

// round 14
// speedup vs baseline: 1.4069x; 1.4069x over previous
#include <cuda_runtime.h>
#include <cuda_fp16.h>
#include <math.h>
#include <stdint.h>

#define NMAX   50000
#define EMAX   800000
#define ETOT   (NMAX + EMAX)
#define HDIM   256
#define DMAX   768
#define NEG_SLOPE 0.2f
#define EPS    1e-16f

// ---------------- scratch ----------------
__device__ float g_bufA[(size_t)NMAX * HDIM];
__device__ float g_bufB[(size_t)NMAX * HDIM];
__device__ __half g_xh[(size_t)NMAX * DMAX];
__device__ __half g_hh[(size_t)NMAX * HDIM];
__device__ __half g_wth[HDIM * DMAX];
__device__ __half g_wth2[HDIM * HDIM];
__device__ float g_asrc[NMAX];
__device__ float g_adst[NMAX];
__device__ float g_gate[NMAX];
__device__ int   g_counts[NMAX];
__device__ int   g_fill[NMAX];
__device__ int   g_rowptr[NMAX + 1];
__device__ int   g_csrc[ETOT];
__device__ int   g_bsum[256];
__device__ int   g_boff[256];
__device__ float g_stats[2];
__device__ float g_partial[256 * 256];

// ---------------- helpers ----------------
__device__ __forceinline__ uint32_t s2u(const void* p) {
    uint32_t a;
    asm("{ .reg .u64 t; cvta.to.shared.u64 t, %1; cvt.u32.u64 %0, t; }" : "=r"(a) : "l"(p));
    return a;
}
__device__ __forceinline__ uint32_t h2u(__half a, __half b) {
    uint16_t ua = *(uint16_t*)&a, ub = *(uint16_t*)&b;
    return (uint32_t)ua | ((uint32_t)ub << 16);
}
__device__ __forceinline__ void ldsm4(uint32_t& r0, uint32_t& r1, uint32_t& r2,
                                      uint32_t& r3, uint32_t addr) {
    asm volatile("ldmatrix.sync.aligned.m8n8.x4.shared.b16 {%0,%1,%2,%3}, [%4];"
                 : "=r"(r0), "=r"(r1), "=r"(r2), "=r"(r3) : "r"(addr));
}
#define MMA_F16(c, a, b) \
    asm volatile("mma.sync.aligned.m16n8k16.row.col.f32.f16.f16.f32 " \
        "{%0,%1,%2,%3}, {%4,%5,%6,%7}, {%8,%9}, {%0,%1,%2,%3};" \
        : "+f"((c)[0]), "+f"((c)[1]), "+f"((c)[2]), "+f"((c)[3]) \
        : "r"((a)[0]), "r"((a)[1]), "r"((a)[2]), "r"((a)[3]), \
          "r"((b)[0]), "r"((b)[1]))
#define CP16(dst, src, sz) \
    asm volatile("cp.async.cg.shared.global [%0], [%1], 16, %2;" \
                 :: "r"(dst), "l"(src), "r"(sz) : "memory")
#define CP_COMMIT() asm volatile("cp.async.commit_group;" ::: "memory")
#define CP_WAIT1()  asm volatile("cp.async.wait_group 1;" ::: "memory")
#define CP_WAIT0()  asm volatile("cp.async.wait_group 0;" ::: "memory")

// ---------------- fp32 -> fp16 convert ----------------
__global__ void k_split(const float* __restrict__ in, __half* __restrict__ hi,
                        int total4) {
    int i = blockIdx.x * blockDim.x + threadIdx.x;
    if (i >= total4) return;
    float4 v = ((const float4*)in)[i];
    ((uint2*)hi)[i] = make_uint2(h2u(__float2half_rn(v.x), __float2half_rn(v.y)),
                                 h2u(__float2half_rn(v.z), __float2half_rn(v.w)));
}

// ---------------- CSR build ----------------
__global__ void k_init_counts(int N) {
    int i = blockIdx.x * blockDim.x + threadIdx.x;
    if (i < N) { g_counts[i] = 1; g_fill[i] = 0; }
}
__global__ void k_hist(const int* __restrict__ ei, int E) {
    int e = blockIdx.x * blockDim.x + threadIdx.x;
    if (e < E) atomicAdd(&g_counts[ei[E + e]], 1);
}
__global__ void k_scan1(int N) {
    __shared__ int red[256];
    int t = threadIdx.x;
    int i = blockIdx.x * 256 + t;
    red[t] = (i < N) ? g_counts[i] : 0;
    __syncthreads();
    for (int off = 128; off > 0; off >>= 1) {
        if (t < off) red[t] += red[t + off];
        __syncthreads();
    }
    if (t == 0) g_bsum[blockIdx.x] = red[0];
}
__global__ void k_scan2(int nb) {
    __shared__ int s[256];
    int t = threadIdx.x;
    s[t] = (t < nb) ? g_bsum[t] : 0;
    __syncthreads();
    for (int off = 1; off < 256; off <<= 1) {
        int v = s[t];
        int add = (t >= off) ? s[t - off] : 0;
        __syncthreads();
        s[t] = v + add;
        __syncthreads();
    }
    if (t < nb) g_boff[t] = (t == 0) ? 0 : s[t - 1];
}
__global__ void k_scan3(int N) {
    __shared__ int s[256];
    int t = threadIdx.x;
    int i = blockIdx.x * 256 + t;
    int c = (i < N) ? g_counts[i] : 0;
    s[t] = c;
    __syncthreads();
    for (int off = 1; off < 256; off <<= 1) {
        int v = s[t];
        int add = (t >= off) ? s[t - off] : 0;
        __syncthreads();
        s[t] = v + add;
        __syncthreads();
    }
    if (i < N) {
        int excl = g_boff[blockIdx.x] + s[t] - c;
        g_rowptr[i] = excl;
        if (i == N - 1) g_rowptr[N] = excl + c;
    }
}
__global__ void k_scatter(const int* __restrict__ ei, int N, int E) {
    int i = blockIdx.x * blockDim.x + threadIdx.x;
    if (i >= N + E) return;
    int s, d;
    if (i < N) { s = i; d = i; }
    else { s = ei[i - N]; d = ei[E + i - N]; }
    int pos = g_rowptr[d] + atomicAdd(&g_fill[d], 1);
    g_csrc[pos] = s;
}

// ---------------- weight transpose to fp16: WT[n][k] = W[k][n] ----------------
__global__ void k_transpose_h(const float* __restrict__ W,
                              __half* __restrict__ WTh, int K, int N) {
    __shared__ float t[32][33];
    int bx = blockIdx.x * 32, by = blockIdx.y * 32;
    int tx = threadIdx.x, ty = threadIdx.y;
#pragma unroll
    for (int j = 0; j < 4; j++) {
        int k = by + ty + j * 8;
        if (k < K && bx + tx < N) t[ty + j * 8][tx] = W[(size_t)k * N + bx + tx];
    }
    __syncthreads();
#pragma unroll
    for (int j = 0; j < 4; j++) {
        int n = bx + ty + j * 8;
        int k = by + tx;
        if (n < N && k < K) WTh[(size_t)n * K + k] = __float2half_rn(t[tx][ty + j * 8]);
    }
}

// ---------------- FP16 tensor-core GEMM, 2-stage cp.async pipeline ----------------
#define ROWB 80
#define OFF_AH 0
#define OFF_BH 10240
#define BUFSZ  20480
#define SMEM_GEMM (2 * BUFSZ)

extern __shared__ __align__(16) uint8_t smx[];

__global__ __launch_bounds__(256) void k_gemm_f16(
        const __half* __restrict__ Ah, const __half* __restrict__ Bh,
        float* __restrict__ C, int M, int K) {
    uint32_t sb = s2u(smx);
    int tid = threadIdx.x;
    int lane = tid & 31, wid = tid >> 5;
    int warp_m = wid >> 2, warp_n = wid & 3;
    int m0 = blockIdx.x * 128, n0 = blockIdx.y * 128;
    int rowsValid = M - m0;
    int nch = K >> 5;

    float c[4][4][4];
#pragma unroll
    for (int i = 0; i < 4; i++)
#pragma unroll
        for (int j = 0; j < 4; j++)
#pragma unroll
            for (int r = 0; r < 4; r++) c[i][j][r] = 0.f;

    int um0 = tid >> 2, ukb = tid & 3;
    int r16 = lane & 15, cblk = lane >> 4;
    uint32_t aBase = (uint32_t)(warp_m * 64 + r16) * ROWB + cblk * 16;
    uint32_t bn = (lane & 7) + ((lane >> 4) << 3);
    uint32_t bkb = (lane >> 3) & 1;
    uint32_t bBase = (uint32_t)(warp_n * 32 + bn) * ROWB + bkb * 16;

    auto stage = [&](int cch, uint32_t bufbase) {
#pragma unroll
        for (int i = 0; i < 2; i++) {
            int m = um0 + i * 64;
            uint32_t doff = bufbase + m * ROWB + ukb * 16;
            uint32_t szA = (m < rowsValid) ? 16u : 0u;
            const __half* pA = Ah + (size_t)(m0 + m) * K + cch * 32 + ukb * 8;
            CP16(sb + OFF_AH + doff, pA, szA);
            const __half* pB = Bh + (size_t)(n0 + m) * K + cch * 32 + ukb * 8;
            CP16(sb + OFF_BH + doff, pB, 16u);
        }
    };

    stage(0, 0);
    CP_COMMIT();

    for (int cch = 0; cch < nch; cch++) {
        uint32_t cur = (uint32_t)(cch & 1) * BUFSZ;
        if (cch + 1 < nch) {
            stage(cch + 1, (uint32_t)((cch + 1) & 1) * BUFSZ);
            CP_COMMIT();
            CP_WAIT1();
        } else {
            CP_WAIT0();
        }
        __syncthreads();

#pragma unroll
        for (int kt = 0; kt < 2; kt++) {
            uint32_t ah[4][4], bh[4][2];
#pragma unroll
            for (int mi = 0; mi < 4; mi++) {
                uint32_t off = cur + aBase + (uint32_t)(mi * 16) * ROWB + kt * 32;
                ldsm4(ah[mi][0], ah[mi][1], ah[mi][2], ah[mi][3], sb + OFF_AH + off);
            }
#pragma unroll
            for (int np = 0; np < 2; np++) {
                uint32_t off = cur + bBase + (uint32_t)(np * 16) * ROWB + kt * 32;
                ldsm4(bh[np * 2][0], bh[np * 2][1], bh[np * 2 + 1][0], bh[np * 2 + 1][1],
                      sb + OFF_BH + off);
            }
#pragma unroll
            for (int mi = 0; mi < 4; mi++)
#pragma unroll
                for (int ni = 0; ni < 4; ni++)
                    MMA_F16(c[mi][ni], ah[mi], bh[ni]);
        }
        __syncthreads();
    }

    int g = lane >> 2, t4 = lane & 3;
#pragma unroll
    for (int mi = 0; mi < 4; mi++) {
#pragma unroll
        for (int ni = 0; ni < 4; ni++) {
            int m = m0 + warp_m * 64 + mi * 16 + g;
            int n = n0 + warp_n * 32 + ni * 8 + t4 * 2;
            if (m < M)
                *(float2*)(C + (size_t)m * HDIM + n) = make_float2(c[mi][ni][0], c[mi][ni][1]);
            if (m + 8 < M)
                *(float2*)(C + (size_t)(m + 8) * HDIM + n) = make_float2(c[mi][ni][2], c[mi][ni][3]);
        }
    }
}

// ---------------- warp-per-node attention scalars ----------------
__global__ __launch_bounds__(256) void k_attw(const float* __restrict__ h,
                                              const float* __restrict__ vs,
                                              const float* __restrict__ vd, int N) {
    int wid = threadIdx.x >> 5, lane = threadIdx.x & 31;
    int n = blockIdx.x * 8 + wid;
    if (n >= N) return;
    const float4* p = (const float4*)(h + (size_t)n * HDIM + lane * 8);
    float4 v0 = p[0], v1 = p[1];
    const float4* s = (const float4*)(vs + lane * 8);
    const float4* d = (const float4*)(vd + lane * 8);
    float4 s0 = s[0], s1 = s[1], d0 = d[0], d1 = d[1];
    float a_s = v0.x * s0.x + v0.y * s0.y + v0.z * s0.z + v0.w * s0.w
              + v1.x * s1.x + v1.y * s1.y + v1.z * s1.z + v1.w * s1.w;
    float a_d = v0.x * d0.x + v0.y * d0.y + v0.z * d0.z + v0.w * d0.w
              + v1.x * d1.x + v1.y * d1.y + v1.z * d1.z + v1.w * d1.w;
#pragma unroll
    for (int off = 16; off > 0; off >>= 1) {
        a_s += __shfl_xor_sync(0xffffffff, a_s, off);
        a_d += __shfl_xor_sync(0xffffffff, a_d, off);
    }
    if (lane == 0) { g_asrc[n] = a_s; g_adst[n] = a_d; }
}

// ---------------- warp-per-node edge softmax + aggregation ----------------
__global__ __launch_bounds__(256) void k_aggw(
        const float* __restrict__ hin, const float* __restrict__ bias,
        float* __restrict__ hout, __half* __restrict__ oh,
        const float* __restrict__ gw, const float* __restrict__ gb,
        int N, int do_split, int do_gate) {
    int wid = threadIdx.x >> 5, lane = threadIdx.x & 31;
    int n = blockIdx.x * 8 + wid;
    if (n >= N) return;
    int begin = g_rowptr[n], end = g_rowptr[n + 1];
    float ad = g_adst[n];

    float m = -1e30f;
    for (int e = begin + lane; e < end; e += 32) {
        float v = g_asrc[g_csrc[e]] + ad;
        v = v > 0.f ? v : NEG_SLOPE * v;
        m = fmaxf(m, v);
    }
#pragma unroll
    for (int off = 16; off > 0; off >>= 1)
        m = fmaxf(m, __shfl_xor_sync(0xffffffff, m, off));

    float4 acc0 = make_float4(0.f, 0.f, 0.f, 0.f);
    float4 acc1 = make_float4(0.f, 0.f, 0.f, 0.f);
    float lsum = 0.f;
    for (int eb = begin; eb < end; eb += 32) {
        int e = eb + lane;
        int cnt = min(32, end - eb);
        float w = 0.f;
        int sreg = 0;
        if (e < end) {
            sreg = g_csrc[e];
            float v = g_asrc[sreg] + ad;
            v = v > 0.f ? v : NEG_SLOPE * v;
            w = expf(v - m);
            lsum += w;
        }
        for (int j = 0; j < cnt; j++) {
            float wj = __shfl_sync(0xffffffff, w, j);
            int sj = __shfl_sync(0xffffffff, sreg, j);
            const float4* p = (const float4*)(hin + (size_t)sj * HDIM + lane * 8);
            float4 v0 = p[0], v1 = p[1];
            acc0.x += wj * v0.x; acc0.y += wj * v0.y;
            acc0.z += wj * v0.z; acc0.w += wj * v0.w;
            acc1.x += wj * v1.x; acc1.y += wj * v1.y;
            acc1.z += wj * v1.z; acc1.w += wj * v1.w;
        }
    }
#pragma unroll
    for (int off = 16; off > 0; off >>= 1)
        lsum += __shfl_xor_sync(0xffffffff, lsum, off);
    float inv = 1.f / (lsum + EPS);

    const float4* b4 = (const float4*)(bias + lane * 8);
    float4 bb0 = b4[0], bb1 = b4[1];
    float4 o0, o1;
    o0.x = fmaxf(acc0.x * inv + bb0.x, 0.f);
    o0.y = fmaxf(acc0.y * inv + bb0.y, 0.f);
    o0.z = fmaxf(acc0.z * inv + bb0.z, 0.f);
    o0.w = fmaxf(acc0.w * inv + bb0.w, 0.f);
    o1.x = fmaxf(acc1.x * inv + bb1.x, 0.f);
    o1.y = fmaxf(acc1.y * inv + bb1.y, 0.f);
    o1.z = fmaxf(acc1.z * inv + bb1.z, 0.f);
    o1.w = fmaxf(acc1.w * inv + bb1.w, 0.f);
    float4* po = (float4*)(hout + (size_t)n * HDIM + lane * 8);
    po[0] = o0; po[1] = o1;

    if (do_split) {
        uint4 hw;
        hw.x = h2u(__float2half_rn(o0.x), __float2half_rn(o0.y));
        hw.y = h2u(__float2half_rn(o0.z), __float2half_rn(o0.w));
        hw.z = h2u(__float2half_rn(o1.x), __float2half_rn(o1.y));
        hw.w = h2u(__float2half_rn(o1.z), __float2half_rn(o1.w));
        *(uint4*)(oh + (size_t)n * HDIM + lane * 8) = hw;
    }
    if (do_gate) {
        const float4* g4 = (const float4*)(gw + lane * 8);
        float4 gg0 = g4[0], gg1 = g4[1];
        float gd = o0.x * gg0.x + o0.y * gg0.y + o0.z * gg0.z + o0.w * gg0.w
                 + o1.x * gg1.x + o1.y * gg1.y + o1.z * gg1.z + o1.w * gg1.w;
#pragma unroll
        for (int off = 16; off > 0; off >>= 1)
            gd += __shfl_xor_sync(0xffffffff, gd, off);
        if (lane == 0) g_gate[n] = gd + gb[0];
    }
}

// ---------------- global attention pooling ----------------
__global__ void k_softmax_stats(int N) {
    __shared__ float red[1024];
    int t = threadIdx.x;
    float m = -1e30f;
    for (int i = t; i < N; i += 1024) m = fmaxf(m, g_gate[i]);
    red[t] = m; __syncthreads();
    for (int off = 512; off > 0; off >>= 1) {
        if (t < off) red[t] = fmaxf(red[t], red[t + off]);
        __syncthreads();
    }
    m = red[0];
    __syncthreads();
    float s = 0.f;
    for (int i = t; i < N; i += 1024) s += expf(g_gate[i] - m);
    red[t] = s; __syncthreads();
    for (int off = 512; off > 0; off >>= 1) {
        if (t < off) red[t] += red[t + off];
        __syncthreads();
    }
    if (t == 0) { g_stats[0] = m; g_stats[1] = red[0]; }
}
__global__ void k_ga_partial(const float* __restrict__ h, int N) {
    int b = blockIdx.x, t = threadIdx.x;
    float m = g_stats[0], S = g_stats[1];
    float acc = 0.f;
    for (int n = b; n < N; n += 256)
        acc += (expf(g_gate[n] - m) / S) * h[(size_t)n * HDIM + t];
    g_partial[b * 256 + t] = acc;
}
__global__ void k_ga_final(float* __restrict__ out) {
    int t = threadIdx.x;
    float acc = 0.f;
    for (int b = 0; b < 256; b++) acc += g_partial[b * 256 + t];
    out[t] = acc;
}

// ---------------- launch ----------------
extern "C" void kernel_launch(void* const* d_in, const int* in_sizes, int n_in,
                              void* d_out, int out_size) {
    const float* x   = (const float*)d_in[0];
    const int*   ei  = (const int*)d_in[1];
    const float* W1  = (const float*)d_in[2];
    const float* b1  = (const float*)d_in[3];
    const float* as1 = (const float*)d_in[4];
    const float* ad1 = (const float*)d_in[5];
    const float* W2  = (const float*)d_in[6];
    const float* b2  = (const float*)d_in[7];
    const float* as2 = (const float*)d_in[8];
    const float* ad2 = (const float*)d_in[9];
    const float* gw  = (const float*)d_in[10];
    const float* gb  = (const float*)d_in[11];
    float*       out = (float*)d_out;

    const int D = 768;
    const int N = in_sizes[0] / D;
    const int E = in_sizes[1] / 2;

    float *bufA, *bufB;
    __half *xh, *hh, *wth, *wth2;
    cudaGetSymbolAddress((void**)&bufA, g_bufA);
    cudaGetSymbolAddress((void**)&bufB, g_bufB);
    cudaGetSymbolAddress((void**)&xh, g_xh);
    cudaGetSymbolAddress((void**)&hh, g_hh);
    cudaGetSymbolAddress((void**)&wth, g_wth);
    cudaGetSymbolAddress((void**)&wth2, g_wth2);

    cudaFuncSetAttribute(k_gemm_f16, cudaFuncAttributeMaxDynamicSharedMemorySize,
                         SMEM_GEMM);

    static cudaStream_t s1 = nullptr, s2 = nullptr;
    static cudaEvent_t e0 = nullptr, e1 = nullptr, e2 = nullptr;
    if (s1 == nullptr) {
        cudaStreamCreateWithFlags(&s1, cudaStreamNonBlocking);
        cudaStreamCreateWithFlags(&s2, cudaStreamNonBlocking);
        cudaEventCreateWithFlags(&e0, cudaEventDisableTiming);
        cudaEventCreateWithFlags(&e1, cudaEventDisableTiming);
        cudaEventCreateWithFlags(&e2, cudaEventDisableTiming);
    }

    int total4 = N * D / 4;
    int nb = (N + 255) / 256;
    dim3 gg((N + 127) / 128, 2);
    int gw8 = (N + 7) / 8;

    // fork
    cudaEventRecord(e0, 0);
    cudaStreamWaitEvent(s1, e0, 0);
    cudaStreamWaitEvent(s2, e0, 0);

    // s1: CSR build chain
    k_init_counts<<<nb, 256, 0, s1>>>(N);
    k_hist<<<(E + 255) / 256, 256, 0, s1>>>(ei, E);
    k_scan1<<<nb, 256, 0, s1>>>(N);
    k_scan2<<<1, 256, 0, s1>>>(nb);
    k_scan3<<<nb, 256, 0, s1>>>(N);
    k_scatter<<<(N + E + 255) / 256, 256, 0, s1>>>(ei, N, E);
    cudaEventRecord(e1, s1);

    // s2: weight transposes (fp16)
    k_transpose_h<<<dim3(HDIM / 32, D / 32), dim3(32, 8), 0, s2>>>(W1, wth, D, HDIM);
    k_transpose_h<<<dim3(HDIM / 32, HDIM / 32), dim3(32, 8), 0, s2>>>(W2, wth2, HDIM, HDIM);
    cudaEventRecord(e2, s2);

    // main: convert x to fp16, layer 1
    k_split<<<(total4 + 255) / 256, 256>>>(x, xh, total4);
    cudaStreamWaitEvent(0, e2, 0);
    k_gemm_f16<<<gg, 256, SMEM_GEMM>>>(xh, wth, bufA, N, D);
    k_attw<<<gw8, 256>>>(bufA, as1, ad1, N);
    cudaStreamWaitEvent(0, e1, 0);
    k_aggw<<<gw8, 256>>>(bufA, b1, bufB, hh, gw, gb, N, 1, 0);

    // layer 2
    k_gemm_f16<<<gg, 256, SMEM_GEMM>>>(hh, wth2, bufA, N, HDIM);
    k_attw<<<gw8, 256>>>(bufA, as2, ad2, N);
    k_aggw<<<gw8, 256>>>(bufA, b2, bufB, hh, gw, gb, N, 0, 1);

    // pooling
    k_softmax_stats<<<1, 1024>>>(N);
    k_ga_partial<<<256, 256>>>(bufB, N);
    k_ga_final<<<1, 256>>>(out);
}

// round 15
// speedup vs baseline: 1.6899x; 1.2011x over previous
#include <cuda_runtime.h>
#include <cuda_fp16.h>
#include <math.h>
#include <stdint.h>

#define NMAX   50000
#define EMAX   800000
#define ETOT   (NMAX + EMAX)
#define HDIM   256
#define DMAX   768
#define NEG_SLOPE 0.2f
#define EPS    1e-16f

// ---------------- scratch ----------------
__device__ float g_bufB[(size_t)NMAX * HDIM];
__device__ __half g_xh[(size_t)NMAX * DMAX];
__device__ __half g_hA[(size_t)NMAX * HDIM];   // fp16 GEMM output
__device__ __half g_hh[(size_t)NMAX * HDIM];   // fp16 layer-1 agg output (GEMM2 input)
__device__ __half g_wth[HDIM * DMAX];
__device__ __half g_wth2[HDIM * HDIM];
__device__ float g_asrc[NMAX];
__device__ float g_adst[NMAX];
__device__ float g_gate[NMAX];
__device__ int   g_counts[NMAX];
__device__ int   g_fill[NMAX];
__device__ int   g_rowptr[NMAX + 1];
__device__ int   g_csrc[ETOT];
__device__ int   g_bsum[256];
__device__ int   g_boff[256];
__device__ float g_stats[2];
__device__ float g_partial[256 * 256];

// ---------------- helpers ----------------
__device__ __forceinline__ uint32_t s2u(const void* p) {
    uint32_t a;
    asm("{ .reg .u64 t; cvta.to.shared.u64 t, %1; cvt.u32.u64 %0, t; }" : "=r"(a) : "l"(p));
    return a;
}
__device__ __forceinline__ uint32_t h2u(__half a, __half b) {
    uint16_t ua = *(uint16_t*)&a, ub = *(uint16_t*)&b;
    return (uint32_t)ua | ((uint32_t)ub << 16);
}
__device__ __forceinline__ void ldsm4(uint32_t& r0, uint32_t& r1, uint32_t& r2,
                                      uint32_t& r3, uint32_t addr) {
    asm volatile("ldmatrix.sync.aligned.m8n8.x4.shared.b16 {%0,%1,%2,%3}, [%4];"
                 : "=r"(r0), "=r"(r1), "=r"(r2), "=r"(r3) : "r"(addr));
}
#define MMA_F16(c, a, b) \
    asm volatile("mma.sync.aligned.m16n8k16.row.col.f32.f16.f16.f32 " \
        "{%0,%1,%2,%3}, {%4,%5,%6,%7}, {%8,%9}, {%0,%1,%2,%3};" \
        : "+f"((c)[0]), "+f"((c)[1]), "+f"((c)[2]), "+f"((c)[3]) \
        : "r"((a)[0]), "r"((a)[1]), "r"((a)[2]), "r"((a)[3]), \
          "r"((b)[0]), "r"((b)[1]))
#define CP16(dst, src, sz) \
    asm volatile("cp.async.cg.shared.global [%0], [%1], 16, %2;" \
                 :: "r"(dst), "l"(src), "r"(sz) : "memory")
#define CP_COMMIT() asm volatile("cp.async.commit_group;" ::: "memory")
#define CP_WAIT1()  asm volatile("cp.async.wait_group 1;" ::: "memory")
#define CP_WAIT0()  asm volatile("cp.async.wait_group 0;" ::: "memory")

// ---------------- fp32 -> fp16 convert ----------------
__global__ void k_split(const float* __restrict__ in, __half* __restrict__ hi,
                        int total4) {
    int i = blockIdx.x * blockDim.x + threadIdx.x;
    if (i >= total4) return;
    float4 v = ((const float4*)in)[i];
    ((uint2*)hi)[i] = make_uint2(h2u(__float2half_rn(v.x), __float2half_rn(v.y)),
                                 h2u(__float2half_rn(v.z), __float2half_rn(v.w)));
}

// ---------------- CSR build ----------------
__global__ void k_init_counts(int N) {
    int i = blockIdx.x * blockDim.x + threadIdx.x;
    if (i < N) { g_counts[i] = 1; g_fill[i] = 0; }
}
__global__ void k_hist(const int* __restrict__ ei, int E) {
    int e = blockIdx.x * blockDim.x + threadIdx.x;
    if (e < E) atomicAdd(&g_counts[ei[E + e]], 1);
}
__global__ void k_scan1(int N) {
    __shared__ int red[256];
    int t = threadIdx.x;
    int i = blockIdx.x * 256 + t;
    red[t] = (i < N) ? g_counts[i] : 0;
    __syncthreads();
    for (int off = 128; off > 0; off >>= 1) {
        if (t < off) red[t] += red[t + off];
        __syncthreads();
    }
    if (t == 0) g_bsum[blockIdx.x] = red[0];
}
__global__ void k_scan2(int nb) {
    __shared__ int s[256];
    int t = threadIdx.x;
    s[t] = (t < nb) ? g_bsum[t] : 0;
    __syncthreads();
    for (int off = 1; off < 256; off <<= 1) {
        int v = s[t];
        int add = (t >= off) ? s[t - off] : 0;
        __syncthreads();
        s[t] = v + add;
        __syncthreads();
    }
    if (t < nb) g_boff[t] = (t == 0) ? 0 : s[t - 1];
}
__global__ void k_scan3(int N) {
    __shared__ int s[256];
    int t = threadIdx.x;
    int i = blockIdx.x * 256 + t;
    int c = (i < N) ? g_counts[i] : 0;
    s[t] = c;
    __syncthreads();
    for (int off = 1; off < 256; off <<= 1) {
        int v = s[t];
        int add = (t >= off) ? s[t - off] : 0;
        __syncthreads();
        s[t] = v + add;
        __syncthreads();
    }
    if (i < N) {
        int excl = g_boff[blockIdx.x] + s[t] - c;
        g_rowptr[i] = excl;
        if (i == N - 1) g_rowptr[N] = excl + c;
    }
}
__global__ void k_scatter(const int* __restrict__ ei, int N, int E) {
    int i = blockIdx.x * blockDim.x + threadIdx.x;
    if (i >= N + E) return;
    int s, d;
    if (i < N) { s = i; d = i; }
    else { s = ei[i - N]; d = ei[E + i - N]; }
    int pos = g_rowptr[d] + atomicAdd(&g_fill[d], 1);
    g_csrc[pos] = s;
}

// ---------------- weight transpose to fp16 ----------------
__global__ void k_transpose_h(const float* __restrict__ W,
                              __half* __restrict__ WTh, int K, int N) {
    __shared__ float t[32][33];
    int bx = blockIdx.x * 32, by = blockIdx.y * 32;
    int tx = threadIdx.x, ty = threadIdx.y;
#pragma unroll
    for (int j = 0; j < 4; j++) {
        int k = by + ty + j * 8;
        if (k < K && bx + tx < N) t[ty + j * 8][tx] = W[(size_t)k * N + bx + tx];
    }
    __syncthreads();
#pragma unroll
    for (int j = 0; j < 4; j++) {
        int n = bx + ty + j * 8;
        int k = by + tx;
        if (n < N && k < K) WTh[(size_t)n * K + k] = __float2half_rn(t[tx][ty + j * 8]);
    }
}

// ---------------- FP16 tensor-core GEMM, fp16 output ----------------
#define ROWB 80
#define OFF_AH 0
#define OFF_BH 10240
#define BUFSZ  20480
#define SMEM_GEMM (2 * BUFSZ)

extern __shared__ __align__(16) uint8_t smx[];

__global__ __launch_bounds__(256) void k_gemm_f16(
        const __half* __restrict__ Ah, const __half* __restrict__ Bh,
        __half* __restrict__ C, int M, int K) {
    uint32_t sb = s2u(smx);
    int tid = threadIdx.x;
    int lane = tid & 31, wid = tid >> 5;
    int warp_m = wid >> 2, warp_n = wid & 3;
    int m0 = blockIdx.x * 128, n0 = blockIdx.y * 128;
    int rowsValid = M - m0;
    int nch = K >> 5;

    float c[4][4][4];
#pragma unroll
    for (int i = 0; i < 4; i++)
#pragma unroll
        for (int j = 0; j < 4; j++)
#pragma unroll
            for (int r = 0; r < 4; r++) c[i][j][r] = 0.f;

    int um0 = tid >> 2, ukb = tid & 3;
    int r16 = lane & 15, cblk = lane >> 4;
    uint32_t aBase = (uint32_t)(warp_m * 64 + r16) * ROWB + cblk * 16;
    uint32_t bn = (lane & 7) + ((lane >> 4) << 3);
    uint32_t bkb = (lane >> 3) & 1;
    uint32_t bBase = (uint32_t)(warp_n * 32 + bn) * ROWB + bkb * 16;

    auto stage = [&](int cch, uint32_t bufbase) {
#pragma unroll
        for (int i = 0; i < 2; i++) {
            int m = um0 + i * 64;
            uint32_t doff = bufbase + m * ROWB + ukb * 16;
            uint32_t szA = (m < rowsValid) ? 16u : 0u;
            const __half* pA = Ah + (size_t)(m0 + m) * K + cch * 32 + ukb * 8;
            CP16(sb + OFF_AH + doff, pA, szA);
            const __half* pB = Bh + (size_t)(n0 + m) * K + cch * 32 + ukb * 8;
            CP16(sb + OFF_BH + doff, pB, 16u);
        }
    };

    stage(0, 0);
    CP_COMMIT();

    for (int cch = 0; cch < nch; cch++) {
        uint32_t cur = (uint32_t)(cch & 1) * BUFSZ;
        if (cch + 1 < nch) {
            stage(cch + 1, (uint32_t)((cch + 1) & 1) * BUFSZ);
            CP_COMMIT();
            CP_WAIT1();
        } else {
            CP_WAIT0();
        }
        __syncthreads();

#pragma unroll
        for (int kt = 0; kt < 2; kt++) {
            uint32_t ah[4][4], bh[4][2];
#pragma unroll
            for (int mi = 0; mi < 4; mi++) {
                uint32_t off = cur + aBase + (uint32_t)(mi * 16) * ROWB + kt * 32;
                ldsm4(ah[mi][0], ah[mi][1], ah[mi][2], ah[mi][3], sb + OFF_AH + off);
            }
#pragma unroll
            for (int np = 0; np < 2; np++) {
                uint32_t off = cur + bBase + (uint32_t)(np * 16) * ROWB + kt * 32;
                ldsm4(bh[np * 2][0], bh[np * 2][1], bh[np * 2 + 1][0], bh[np * 2 + 1][1],
                      sb + OFF_BH + off);
            }
#pragma unroll
            for (int mi = 0; mi < 4; mi++)
#pragma unroll
                for (int ni = 0; ni < 4; ni++)
                    MMA_F16(c[mi][ni], ah[mi], bh[ni]);
        }
        __syncthreads();
    }

    // epilogue: fp16 output
    int g = lane >> 2, t4 = lane & 3;
#pragma unroll
    for (int mi = 0; mi < 4; mi++) {
#pragma unroll
        for (int ni = 0; ni < 4; ni++) {
            int m = m0 + warp_m * 64 + mi * 16 + g;
            int n = n0 + warp_n * 32 + ni * 8 + t4 * 2;
            if (m < M)
                *(uint32_t*)(C + (size_t)m * HDIM + n) =
                    h2u(__float2half_rn(c[mi][ni][0]), __float2half_rn(c[mi][ni][1]));
            if (m + 8 < M)
                *(uint32_t*)(C + (size_t)(m + 8) * HDIM + n) =
                    h2u(__float2half_rn(c[mi][ni][2]), __float2half_rn(c[mi][ni][3]));
        }
    }
}

// ---------------- warp-per-node attention scalars (fp16 h) ----------------
__global__ __launch_bounds__(256) void k_attw(const __half* __restrict__ h,
                                              const float* __restrict__ vs,
                                              const float* __restrict__ vd, int N) {
    int wid = threadIdx.x >> 5, lane = threadIdx.x & 31;
    int n = blockIdx.x * 8 + wid;
    if (n >= N) return;
    uint4 hv = *(const uint4*)(h + (size_t)n * HDIM + lane * 8);
    float2 f0 = __half22float2(*(__half2*)&hv.x);
    float2 f1 = __half22float2(*(__half2*)&hv.y);
    float2 f2 = __half22float2(*(__half2*)&hv.z);
    float2 f3 = __half22float2(*(__half2*)&hv.w);
    const float4* s = (const float4*)(vs + lane * 8);
    const float4* d = (const float4*)(vd + lane * 8);
    float4 s0 = s[0], s1 = s[1], d0 = d[0], d1 = d[1];
    float a_s = f0.x * s0.x + f0.y * s0.y + f1.x * s0.z + f1.y * s0.w
              + f2.x * s1.x + f2.y * s1.y + f3.x * s1.z + f3.y * s1.w;
    float a_d = f0.x * d0.x + f0.y * d0.y + f1.x * d0.z + f1.y * d0.w
              + f2.x * d1.x + f2.y * d1.y + f3.x * d1.z + f3.y * d1.w;
#pragma unroll
    for (int off = 16; off > 0; off >>= 1) {
        a_s += __shfl_xor_sync(0xffffffff, a_s, off);
        a_d += __shfl_xor_sync(0xffffffff, a_d, off);
    }
    if (lane == 0) { g_asrc[n] = a_s; g_adst[n] = a_d; }
}

// ---------------- warp-per-node edge softmax + aggregation (fp16 gather) ----------------
__global__ __launch_bounds__(256) void k_aggw(
        const __half* __restrict__ hin, const float* __restrict__ bias,
        float* __restrict__ hout, __half* __restrict__ oh,
        const float* __restrict__ gw, const float* __restrict__ gb,
        int N, int do_out, int do_split, int do_gate) {
    int wid = threadIdx.x >> 5, lane = threadIdx.x & 31;
    int n = blockIdx.x * 8 + wid;
    if (n >= N) return;
    int begin = g_rowptr[n], end = g_rowptr[n + 1];
    float ad = g_adst[n];

    float m = -1e30f;
    for (int e = begin + lane; e < end; e += 32) {
        float v = g_asrc[g_csrc[e]] + ad;
        v = v > 0.f ? v : NEG_SLOPE * v;
        m = fmaxf(m, v);
    }
#pragma unroll
    for (int off = 16; off > 0; off >>= 1)
        m = fmaxf(m, __shfl_xor_sync(0xffffffff, m, off));

    float4 acc0 = make_float4(0.f, 0.f, 0.f, 0.f);
    float4 acc1 = make_float4(0.f, 0.f, 0.f, 0.f);
    float lsum = 0.f;
    for (int eb = begin; eb < end; eb += 32) {
        int e = eb + lane;
        int cnt = min(32, end - eb);
        float w = 0.f;
        int sreg = 0;
        if (e < end) {
            sreg = g_csrc[e];
            float v = g_asrc[sreg] + ad;
            v = v > 0.f ? v : NEG_SLOPE * v;
            w = expf(v - m);
            lsum += w;
        }
        for (int j = 0; j < cnt; j++) {
            float wj = __shfl_sync(0xffffffff, w, j);
            int sj = __shfl_sync(0xffffffff, sreg, j);
            uint4 hv = *(const uint4*)(hin + (size_t)sj * HDIM + lane * 8);
            float2 f0 = __half22float2(*(__half2*)&hv.x);
            float2 f1 = __half22float2(*(__half2*)&hv.y);
            float2 f2 = __half22float2(*(__half2*)&hv.z);
            float2 f3 = __half22float2(*(__half2*)&hv.w);
            acc0.x += wj * f0.x; acc0.y += wj * f0.y;
            acc0.z += wj * f1.x; acc0.w += wj * f1.y;
            acc1.x += wj * f2.x; acc1.y += wj * f2.y;
            acc1.z += wj * f3.x; acc1.w += wj * f3.y;
        }
    }
#pragma unroll
    for (int off = 16; off > 0; off >>= 1)
        lsum += __shfl_xor_sync(0xffffffff, lsum, off);
    float inv = 1.f / (lsum + EPS);

    const float4* b4 = (const float4*)(bias + lane * 8);
    float4 bb0 = b4[0], bb1 = b4[1];
    float4 o0, o1;
    o0.x = fmaxf(acc0.x * inv + bb0.x, 0.f);
    o0.y = fmaxf(acc0.y * inv + bb0.y, 0.f);
    o0.z = fmaxf(acc0.z * inv + bb0.z, 0.f);
    o0.w = fmaxf(acc0.w * inv + bb0.w, 0.f);
    o1.x = fmaxf(acc1.x * inv + bb1.x, 0.f);
    o1.y = fmaxf(acc1.y * inv + bb1.y, 0.f);
    o1.z = fmaxf(acc1.z * inv + bb1.z, 0.f);
    o1.w = fmaxf(acc1.w * inv + bb1.w, 0.f);
    if (do_out) {
        float4* po = (float4*)(hout + (size_t)n * HDIM + lane * 8);
        po[0] = o0; po[1] = o1;
    }
    if (do_split) {
        uint4 hw;
        hw.x = h2u(__float2half_rn(o0.x), __float2half_rn(o0.y));
        hw.y = h2u(__float2half_rn(o0.z), __float2half_rn(o0.w));
        hw.z = h2u(__float2half_rn(o1.x), __float2half_rn(o1.y));
        hw.w = h2u(__float2half_rn(o1.z), __float2half_rn(o1.w));
        *(uint4*)(oh + (size_t)n * HDIM + lane * 8) = hw;
    }
    if (do_gate) {
        const float4* g4 = (const float4*)(gw + lane * 8);
        float4 gg0 = g4[0], gg1 = g4[1];
        float gd = o0.x * gg0.x + o0.y * gg0.y + o0.z * gg0.z + o0.w * gg0.w
                 + o1.x * gg1.x + o1.y * gg1.y + o1.z * gg1.z + o1.w * gg1.w;
#pragma unroll
        for (int off = 16; off > 0; off >>= 1)
            gd += __shfl_xor_sync(0xffffffff, gd, off);
        if (lane == 0) g_gate[n] = gd + gb[0];
    }
}

// ---------------- global attention pooling ----------------
__global__ void k_softmax_stats(int N) {
    __shared__ float red[1024];
    int t = threadIdx.x;
    float m = -1e30f;
    for (int i = t; i < N; i += 1024) m = fmaxf(m, g_gate[i]);
    red[t] = m; __syncthreads();
    for (int off = 512; off > 0; off >>= 1) {
        if (t < off) red[t] = fmaxf(red[t], red[t + off]);
        __syncthreads();
    }
    m = red[0];
    __syncthreads();
    float s = 0.f;
    for (int i = t; i < N; i += 1024) s += expf(g_gate[i] - m);
    red[t] = s; __syncthreads();
    for (int off = 512; off > 0; off >>= 1) {
        if (t < off) red[t] += red[t + off];
        __syncthreads();
    }
    if (t == 0) { g_stats[0] = m; g_stats[1] = red[0]; }
}
__global__ void k_ga_partial(const float* __restrict__ h, int N) {
    int b = blockIdx.x, t = threadIdx.x;
    float m = g_stats[0], S = g_stats[1];
    float acc = 0.f;
    for (int n = b; n < N; n += 256)
        acc += (expf(g_gate[n] - m) / S) * h[(size_t)n * HDIM + t];
    g_partial[b * 256 + t] = acc;
}
__global__ void k_ga_final(float* __restrict__ out) {
    int t = threadIdx.x;
    float acc = 0.f;
    for (int b = 0; b < 256; b++) acc += g_partial[b * 256 + t];
    out[t] = acc;
}

// ---------------- launch ----------------
extern "C" void kernel_launch(void* const* d_in, const int* in_sizes, int n_in,
                              void* d_out, int out_size) {
    const float* x   = (const float*)d_in[0];
    const int*   ei  = (const int*)d_in[1];
    const float* W1  = (const float*)d_in[2];
    const float* b1  = (const float*)d_in[3];
    const float* as1 = (const float*)d_in[4];
    const float* ad1 = (const float*)d_in[5];
    const float* W2  = (const float*)d_in[6];
    const float* b2  = (const float*)d_in[7];
    const float* as2 = (const float*)d_in[8];
    const float* ad2 = (const float*)d_in[9];
    const float* gw  = (const float*)d_in[10];
    const float* gb  = (const float*)d_in[11];
    float*       out = (float*)d_out;

    const int D = 768;
    const int N = in_sizes[0] / D;
    const int E = in_sizes[1] / 2;

    float *bufB;
    __half *xh, *hA, *hh, *wth, *wth2;
    cudaGetSymbolAddress((void**)&bufB, g_bufB);
    cudaGetSymbolAddress((void**)&xh, g_xh);
    cudaGetSymbolAddress((void**)&hA, g_hA);
    cudaGetSymbolAddress((void**)&hh, g_hh);
    cudaGetSymbolAddress((void**)&wth, g_wth);
    cudaGetSymbolAddress((void**)&wth2, g_wth2);

    cudaFuncSetAttribute(k_gemm_f16, cudaFuncAttributeMaxDynamicSharedMemorySize,
                         SMEM_GEMM);

    static cudaStream_t s1 = nullptr, s2 = nullptr;
    static cudaEvent_t e0 = nullptr, e1 = nullptr, e2 = nullptr;
    if (s1 == nullptr) {
        cudaStreamCreateWithFlags(&s1, cudaStreamNonBlocking);
        cudaStreamCreateWithFlags(&s2, cudaStreamNonBlocking);
        cudaEventCreateWithFlags(&e0, cudaEventDisableTiming);
        cudaEventCreateWithFlags(&e1, cudaEventDisableTiming);
        cudaEventCreateWithFlags(&e2, cudaEventDisableTiming);
    }

    int total4 = N * D / 4;
    int nb = (N + 255) / 256;
    dim3 gg((N + 127) / 128, 2);
    int gw8 = (N + 7) / 8;

    // fork
    cudaEventRecord(e0, 0);
    cudaStreamWaitEvent(s1, e0, 0);
    cudaStreamWaitEvent(s2, e0, 0);

    // s1: CSR build chain
    k_init_counts<<<nb, 256, 0, s1>>>(N);
    k_hist<<<(E + 255) / 256, 256, 0, s1>>>(ei, E);
    k_scan1<<<nb, 256, 0, s1>>>(N);
    k_scan2<<<1, 256, 0, s1>>>(nb);
    k_scan3<<<nb, 256, 0, s1>>>(N);
    k_scatter<<<(N + E + 255) / 256, 256, 0, s1>>>(ei, N, E);
    cudaEventRecord(e1, s1);

    // s2: weight transposes (fp16)
    k_transpose_h<<<dim3(HDIM / 32, D / 32), dim3(32, 8), 0, s2>>>(W1, wth, D, HDIM);
    k_transpose_h<<<dim3(HDIM / 32, HDIM / 32), dim3(32, 8), 0, s2>>>(W2, wth2, HDIM, HDIM);
    cudaEventRecord(e2, s2);

    // main: convert x to fp16, layer 1
    k_split<<<(total4 + 255) / 256, 256>>>(x, xh, total4);
    cudaStreamWaitEvent(0, e2, 0);
    k_gemm_f16<<<gg, 256, SMEM_GEMM>>>(xh, wth, hA, N, D);
    k_attw<<<gw8, 256>>>(hA, as1, ad1, N);
    cudaStreamWaitEvent(0, e1, 0);
    k_aggw<<<gw8, 256>>>(hA, b1, bufB, hh, gw, gb, N, 0, 1, 0);

    // layer 2
    k_gemm_f16<<<gg, 256, SMEM_GEMM>>>(hh, wth2, hA, N, HDIM);
    k_attw<<<gw8, 256>>>(hA, as2, ad2, N);
    k_aggw<<<gw8, 256>>>(hA, b2, bufB, hh, gw, gb, N, 1, 0, 1);

    // pooling
    k_softmax_stats<<<1, 1024>>>(N);
    k_ga_partial<<<256, 256>>>(bufB, N);
    k_ga_final<<<1, 256>>>(out);
}